// round 13
// baseline (speedup 1.0000x reference)
#include <cuda_runtime.h>

// YoloLoss: input/target (256, 25, 64, 64) f32 -> scalar f32.
// Row i = (b, y, x). Element (i, c) at base(b) + c*4096 + (i & 4095).
// Each thread handles 4 consecutive rows (one float4 per channel).
//
// R6 structure (best: 35.6us, DRAM 77.4%) + register-free MLP:
// prefetch.global.L2 for all 40 class-plane lines at kernel start
// (one lane per 128B line), overlapping HBM->L2 with the box phase.
// Tail: per-block fp32 partial -> i64 fixed point (x2^30, exact via double)
// -> atomicAdd(u64) => bit-deterministic; last block writes out + resets.

#define NROWS   (256 * 64 * 64)      // 1,048,576
#define GROUPS  (NROWS / 4)          // 262,144
#define THREADS 256
#define BLOCKS  (GROUPS / THREADS)   // 1024

#define COORD_W 5.0f
#define NOOBJ_W 0.5f
#define INV_BLOCKS (1.0f / 64.0f)
#define FP_SCALE 1073741824.0        // 2^30

__device__ unsigned long long g_sum;        // zero-init; reset by finisher
__device__ unsigned int       g_done_count; // zero-init; reset by finisher

__global__ void __launch_bounds__(THREADS, 4) yolo_loss_fused(
    const float* __restrict__ inp, const float* __restrict__ tgt,
    float* __restrict__ out)
{
    const int gid = blockIdx.x * THREADS + threadIdx.x;
    const int i0  = gid << 2;                 // first of 4 rows
    const int b   = i0 >> 12;                 // / 4096
    const int off = i0 & 4095;
    const float* __restrict__ pb = inp + (size_t)b * (25 * 4096) + off;
    const float* __restrict__ tb = tgt + (size_t)b * (25 * 4096) + off;

    // Register-free lookahead: prefetch all class-plane lines into L2.
    // One lane per 128B line (8 threads x float4 = 1 line).
    if ((threadIdx.x & 7) == 0) {
#pragma unroll
        for (int c = 5; c < 25; c++) {
            asm volatile("prefetch.global.L2 [%0];" :: "l"(pb + c * 4096));
            asm volatile("prefetch.global.L2 [%0];" :: "l"(tb + c * 4096));
        }
    }

    // Front-batched loads of the 5 box channels (10x LDG.128).
    float P[5][4], T[5][4];
#pragma unroll
    for (int c = 0; c < 5; c++) {
        float4 pv = *reinterpret_cast<const float4*>(pb + c * 4096);
        float4 tv = *reinterpret_cast<const float4*>(tb + c * 4096);
        P[c][0] = pv.x; P[c][1] = pv.y; P[c][2] = pv.z; P[c][3] = pv.w;
        T[c][0] = tv.x; T[c][1] = tv.y; T[c][2] = tv.z; T[c][3] = tv.w;
    }

    float m[4];
    float lsum = 0.0f;

#pragma unroll
    for (int l = 0; l < 4; l++) {
        const float p0 = P[0][l], p1 = P[1][l], p2 = P[2][l], p3 = P[3][l], p4 = P[4][l];
        const float t0 = T[0][l], t1 = T[1][l], t2 = T[2][l], t3 = T[3][l], t4 = T[4][l];

        const float mm = (t4 > 0.0f) ? 1.0f : 0.0f;
        m[l] = mm;

        const float c1x = p0 * INV_BLOCKS, c1y = p1 * INV_BLOCKS;
        const float c2x = t0 * INV_BLOCKS, c2y = t1 * INV_BLOCKS;
        const float x1a = c1x - 0.5f * p2, x2a = c1x + 0.5f * p2;
        const float y1a = c1y - 0.5f * p3, y2a = c1y + 0.5f * p3;
        const float x1b = c2x - 0.5f * t2, x2b = c2x + 0.5f * t2;
        const float y1b = c2y - 0.5f * t3, y2b = c2y + 0.5f * t3;
        const float dx = fminf(x2a, x2b) - fmaxf(x1a, x1b);
        const float dy = fminf(y2a, y2b) - fmaxf(y1a, y1b);
        const float inter = dx * dy;
        const float uni   = p2 * p3 + t2 * t3 - inter;
        const bool  pos   = (dx > 0.0f) && (dy > 0.0f);
        const float iou   = pos ? (inter / uni) : 0.0f;

        const float sp2 = sqrtf(p2), sp3 = sqrtf(p3);
        const float st2 = sqrtf(t2), st3 = sqrtf(t3);

        const float dxy = (p0 - t0) * (p0 - t0) + (p1 - t1) * (p1 - t1);
        const float dwh = (sp2 - st2) * (sp2 - st2) + (sp3 - st3) * (sp3 - st3);
        const float dcf = (p4 - iou) * (p4 - iou);
        const float dnb = p4 * p4;

        lsum += mm * (COORD_W * (dxy + dwh) + dcf)
              + NOOBJ_W * (1.0f - mm) * dnb;
    }

    // Class channels 5..24: streamed float4 loads (should hit L2 now).
#pragma unroll
    for (int c = 5; c < 25; c++) {
        float4 pv = *reinterpret_cast<const float4*>(pb + c * 4096);
        float4 tv = *reinterpret_cast<const float4*>(tb + c * 4096);
        float d0 = pv.x - tv.x, d1 = pv.y - tv.y, d2 = pv.z - tv.z, d3 = pv.w - tv.w;
        lsum += m[0] * d0 * d0 + m[1] * d1 * d1 + m[2] * d2 * d2 + m[3] * d3 * d3;
    }

    // Warp reduce.
#pragma unroll
    for (int o = 16; o > 0; o >>= 1)
        lsum += __shfl_xor_sync(0xFFFFFFFFu, lsum, o);

    __shared__ float ws[THREADS / 32];
    const int lane = threadIdx.x & 31;
    const int warp = threadIdx.x >> 5;
    if (lane == 0) ws[warp] = lsum;
    __syncthreads();

    if (threadIdx.x == 0) {
        float v = 0.0f;
#pragma unroll
        for (int w = 0; w < THREADS / 32; w++) v += ws[w];

        long long q = __double2ll_rn((double)v * FP_SCALE);
        atomicAdd(&g_sum, (unsigned long long)q);   // order-independent
        __threadfence();
        unsigned int prev = atomicAdd(&g_done_count, 1u);
        if (prev == BLOCKS - 1) {
            unsigned long long total = atomicAdd(&g_sum, 0ULL);
            out[0] = (float)((double)(long long)total * (1.0 / FP_SCALE));
            g_done_count = 0;   // reset for next graph replay
            g_sum = 0ULL;
            __threadfence();
        }
    }
}

extern "C" void kernel_launch(void* const* d_in, const int* in_sizes, int n_in,
                              void* d_out, int out_size)
{
    const float* inp = (const float*)d_in[0];
    const float* tgt = (const float*)d_in[1];
    float* out = (float*)d_out;

    yolo_loss_fused<<<BLOCKS, THREADS>>>(inp, tgt, out);
}

// round 14
// speedup vs baseline: 1.2293x; 1.2293x over previous
#include <cuda_runtime.h>

// YoloLoss: input/target (256, 25, 64, 64) f32 -> scalar f32.
// Row i = (b, y, x). Element (i, c) at base(b) + c*4096 + (i & 4095).
// Each thread handles 4 consecutive rows (one float4 per channel).
//
// R6 schedule with two micro-changes:
//  - THREADS=128, cap(,8): same 32 warps/SM + 64-reg budget, finer CTA
//    drain granularity (smaller end-of-kernel skew) and cheaper block reduce.
//  - __fdividef for iou: shorter serial chain in the box phase.
// Tail: per-block fp32 partial -> i64 fixed point (x2^30, exact via double)
// -> atomicAdd(u64) => bit-deterministic; last block writes out + resets.

#define NROWS   (256 * 64 * 64)      // 1,048,576
#define GROUPS  (NROWS / 4)          // 262,144
#define THREADS 128
#define BLOCKS  (GROUPS / THREADS)   // 2048

#define COORD_W 5.0f
#define NOOBJ_W 0.5f
#define INV_BLOCKS (1.0f / 64.0f)
#define FP_SCALE 1073741824.0        // 2^30

__device__ unsigned long long g_sum;        // zero-init; reset by finisher
__device__ unsigned int       g_done_count; // zero-init; reset by finisher

__global__ void __launch_bounds__(THREADS, 8) yolo_loss_fused(
    const float* __restrict__ inp, const float* __restrict__ tgt,
    float* __restrict__ out)
{
    const int gid = blockIdx.x * THREADS + threadIdx.x;
    const int i0  = gid << 2;                 // first of 4 rows
    const int b   = i0 >> 12;                 // / 4096
    const int off = i0 & 4095;
    const float* __restrict__ pb = inp + (size_t)b * (25 * 4096) + off;
    const float* __restrict__ tb = tgt + (size_t)b * (25 * 4096) + off;

    // Front-batched loads of the 5 box channels (10x LDG.128).
    float P[5][4], T[5][4];
#pragma unroll
    for (int c = 0; c < 5; c++) {
        float4 pv = *reinterpret_cast<const float4*>(pb + c * 4096);
        float4 tv = *reinterpret_cast<const float4*>(tb + c * 4096);
        P[c][0] = pv.x; P[c][1] = pv.y; P[c][2] = pv.z; P[c][3] = pv.w;
        T[c][0] = tv.x; T[c][1] = tv.y; T[c][2] = tv.z; T[c][3] = tv.w;
    }

    float m[4];
    float lsum = 0.0f;

#pragma unroll
    for (int l = 0; l < 4; l++) {
        const float p0 = P[0][l], p1 = P[1][l], p2 = P[2][l], p3 = P[3][l], p4 = P[4][l];
        const float t0 = T[0][l], t1 = T[1][l], t2 = T[2][l], t3 = T[3][l], t4 = T[4][l];

        const float mm = (t4 > 0.0f) ? 1.0f : 0.0f;
        m[l] = mm;

        const float c1x = p0 * INV_BLOCKS, c1y = p1 * INV_BLOCKS;
        const float c2x = t0 * INV_BLOCKS, c2y = t1 * INV_BLOCKS;
        const float x1a = c1x - 0.5f * p2, x2a = c1x + 0.5f * p2;
        const float y1a = c1y - 0.5f * p3, y2a = c1y + 0.5f * p3;
        const float x1b = c2x - 0.5f * t2, x2b = c2x + 0.5f * t2;
        const float y1b = c2y - 0.5f * t3, y2b = c2y + 0.5f * t3;
        const float dx = fminf(x2a, x2b) - fmaxf(x1a, x1b);
        const float dy = fminf(y2a, y2b) - fmaxf(y1a, y1b);
        const float inter = dx * dy;
        const float uni   = p2 * p3 + t2 * t3 - inter;
        const bool  pos   = (dx > 0.0f) && (dy > 0.0f);
        const float iou   = pos ? __fdividef(inter, uni) : 0.0f;

        const float sp2 = sqrtf(p2), sp3 = sqrtf(p3);
        const float st2 = sqrtf(t2), st3 = sqrtf(t3);

        const float dxy = (p0 - t0) * (p0 - t0) + (p1 - t1) * (p1 - t1);
        const float dwh = (sp2 - st2) * (sp2 - st2) + (sp3 - st3) * (sp3 - st3);
        const float dcf = (p4 - iou) * (p4 - iou);
        const float dnb = p4 * p4;

        lsum += mm * (COORD_W * (dxy + dwh) + dcf)
              + NOOBJ_W * (1.0f - mm) * dnb;
    }

    // Class channels 5..24: streamed float4 loads.
#pragma unroll
    for (int c = 5; c < 25; c++) {
        float4 pv = *reinterpret_cast<const float4*>(pb + c * 4096);
        float4 tv = *reinterpret_cast<const float4*>(tb + c * 4096);
        float d0 = pv.x - tv.x, d1 = pv.y - tv.y, d2 = pv.z - tv.z, d3 = pv.w - tv.w;
        lsum += m[0] * d0 * d0 + m[1] * d1 * d1 + m[2] * d2 * d2 + m[3] * d3 * d3;
    }

    // Warp reduce.
#pragma unroll
    for (int o = 16; o > 0; o >>= 1)
        lsum += __shfl_xor_sync(0xFFFFFFFFu, lsum, o);

    __shared__ float ws[THREADS / 32];
    const int lane = threadIdx.x & 31;
    const int warp = threadIdx.x >> 5;
    if (lane == 0) ws[warp] = lsum;
    __syncthreads();

    if (threadIdx.x == 0) {
        float v = 0.0f;
#pragma unroll
        for (int w = 0; w < THREADS / 32; w++) v += ws[w];

        long long q = __double2ll_rn((double)v * FP_SCALE);
        atomicAdd(&g_sum, (unsigned long long)q);   // order-independent
        __threadfence();
        unsigned int prev = atomicAdd(&g_done_count, 1u);
        if (prev == BLOCKS - 1) {
            unsigned long long total = atomicAdd(&g_sum, 0ULL);
            out[0] = (float)((double)(long long)total * (1.0 / FP_SCALE));
            g_done_count = 0;   // reset for next graph replay
            g_sum = 0ULL;
            __threadfence();
        }
    }
}

extern "C" void kernel_launch(void* const* d_in, const int* in_sizes, int n_in,
                              void* d_out, int out_size)
{
    const float* inp = (const float*)d_in[0];
    const float* tgt = (const float*)d_in[1];
    float* out = (float*)d_out;

    yolo_loss_fused<<<BLOCKS, THREADS>>>(inp, tgt, out);
}